// round 3
// baseline (speedup 1.0000x reference)
#include <cuda_runtime.h>
#include <cuda_bf16.h>

typedef unsigned long long ull;

#define H      51
#define G4     204        // 4*H
#define HP     52         // padded hidden (even, for f32x2 pairs)
#define NP     26         // packed h-pairs per gate row
#define T_LEN  2048
#define N_SEQ  1024
#define S      4          // sequences per block
#define TPB    128
#define XT     32         // stimulus prefetch tile (steps)

// ---------------- f32x2 helpers (Blackwell packed fp32) ----------------
__device__ __forceinline__ ull ffma2(ull a, ull b, ull c) {
    ull d;
    asm("fma.rn.f32x2 %0, %1, %2, %3;" : "=l"(d) : "l"(a), "l"(b), "l"(c));
    return d;
}
__device__ __forceinline__ ull pack2(float lo, float hi) {
    ull d;
    asm("mov.b64 %0, {%1, %2};" : "=l"(d) : "f"(lo), "f"(hi));
    return d;
}
__device__ __forceinline__ float lo2(ull v) { return __uint_as_float((unsigned)v); }
__device__ __forceinline__ float hi2(ull v) { return __uint_as_float((unsigned)(v >> 32)); }

// ---------------- activations (MUFU-based, ~1e-7 accurate) -------------
__device__ __forceinline__ float sigmoidf_(float x) { return 1.0f / (1.0f + __expf(-x)); }
__device__ __forceinline__ float tanhf_(float x)    { return 1.0f - 2.0f / (__expf(2.0f * x) + 1.0f); }

__global__ void __launch_bounds__(TPB, 2) lstm2_kernel(
    const float* __restrict__ stim,
    const float* __restrict__ Wih1, const float* __restrict__ Whh1,
    const float* __restrict__ bih1, const float* __restrict__ bhh1,
    const float* __restrict__ Wih2, const float* __restrict__ Whh2,
    const float* __restrict__ bih2, const float* __restrict__ bhh2,
    float* __restrict__ out)
{
    __shared__ __align__(16) float h1s[S][HP];     // layer-1 hidden state (padded, [51]=0)
    __shared__ float gsm[S][G4];                   // layer-1 pre-activation gates
    __shared__ float xbuf[2][S][XT];               // double-buffered stimulus tiles
    __shared__ float h2buf[S][XT];                 // layer-2 outputs, flushed per tile
    __shared__ ull   w2p[4][NP];                   // W_ih2 packed along h

    const int tid  = threadIdx.x;
    const int seq0 = blockIdx.x * S;

    // ---- layer-1 gate-row assignment: thread owns rows r0=tid, r1=tid+128 (if <204)
    const int  r0   = tid;
    const bool has1 = (tid + TPB) < G4;           // tid < 76
    const int  r1   = has1 ? (tid + TPB) : 0;

    // recurrent weights packed along h, register-resident
    ull w0[NP], w1[NP];
#pragma unroll
    for (int p = 0; p < NP; ++p) {
        float a0 = Whh1[r0 * H + 2 * p];
        float a1 = (2 * p + 1 < H) ? Whh1[r0 * H + 2 * p + 1] : 0.0f;
        w0[p] = pack2(a0, a1);
        float b0v = has1 ? Whh1[r1 * H + 2 * p] : 0.0f;
        float b1v = (has1 && (2 * p + 1 < H)) ? Whh1[r1 * H + 2 * p + 1] : 0.0f;
        w1[p] = pack2(b0v, b1v);
    }
    const float bs0 = bih1[r0] + bhh1[r0];
    const float bs1 = has1 ? (bih1[r1] + bhh1[r1]) : 0.0f;
    const float wi0 = Wih1[r0];
    const float wi1 = has1 ? Wih1[r1] : 0.0f;

    // ---- elementwise task assignment: task = (s,j) flat id; A = tid, B = tid+128
    const int  idA = tid;                  // 0..127 < 204
    const int  sA = idA / H, jA = idA % H;
    const bool hasB = tid < (G4 - TPB);    // tid < 76
    const int  idB = hasB ? (tid + TPB) : 0;
    const int  sB = idB / H, jB = idB % H;
    float c1A = 0.0f, c1B = 0.0f;

    // ---- layer-2 state: lanes 0..15 of warp 0, thread = (s2, g2)
    float whh2g = 0.0f, b2sum = 0.0f, h2r = 0.0f, c2r = 0.0f;
    int s2 = 0, g2 = 0;
    if (tid < 16) {
        s2 = tid >> 2; g2 = tid & 3;
        whh2g = Whh2[g2];
        b2sum = bih2[g2] + bhh2[g2];
    }

    // ---- init shared memory
    for (int i = tid; i < S * HP; i += TPB) (&h1s[0][0])[i] = 0.0f;
    if (tid < 4) {
#pragma unroll
        for (int p = 0; p < NP; ++p) {
            float a = Wih2[tid * H + 2 * p];
            float b = (2 * p + 1 < H) ? Wih2[tid * H + 2 * p + 1] : 0.0f;
            w2p[tid][p] = pack2(a, b);
        }
    }
    // stimulus prefetch (warp 3): tile 0 -> smem, tile 1 -> regs
    float xr[S];
    if (tid >= 96) {
        int lane = tid - 96;
#pragma unroll
        for (int s = 0; s < S; ++s)
            xbuf[0][s][lane] = stim[(seq0 + s) * T_LEN + lane];
#pragma unroll
        for (int s = 0; s < S; ++s)
            xr[s] = stim[(seq0 + s) * T_LEN + XT + lane];
    }
    __syncthreads();

    for (int t = 0; t < T_LEN; ++t) {
        const int cur = (t >> 5) & 1;
        const int tp  = t & (XT - 1);

        // ---- tile boundary: publish prefetched x tile, start next LDG
        if (tp == 0 && t != 0) {
            if (tid >= 96) {
                int lane = tid - 96;
#pragma unroll
                for (int s = 0; s < S; ++s) xbuf[cur][s][lane] = xr[s];
                int nt = t + XT;
                if (nt < T_LEN) {
#pragma unroll
                    for (int s = 0; s < S; ++s)
                        xr[s] = stim[(seq0 + s) * T_LEN + nt + lane];
                }
            }
            __syncthreads();
        }

        // ---- phase A: gates = W_hh1 @ h1 + b + x*W_ih1  (f32x2 along h)
#pragma unroll
        for (int s = 0; s < S; ++s) {
            const ull* hp = (const ull*)(&h1s[s][0]);
            ull a00 = 0, a01 = 0, a10 = 0, a11 = 0;
#pragma unroll
            for (int p = 0; p < NP; p += 2) {
                ull hv0 = hp[p];
                ull hv1 = hp[p + 1];
                a00 = ffma2(w0[p],     hv0, a00);
                a10 = ffma2(w1[p],     hv0, a10);
                a01 = ffma2(w0[p + 1], hv1, a01);
                a11 = ffma2(w1[p + 1], hv1, a11);
            }
            const float xv = xbuf[cur][s][tp];
            float g0 = lo2(a00) + hi2(a00) + lo2(a01) + hi2(a01) + bs0 + xv * wi0;
            gsm[s][r0] = g0;
            if (has1) {
                float g1 = lo2(a10) + hi2(a10) + lo2(a11) + hi2(a11) + bs1 + xv * wi1;
                gsm[s][r1] = g1;
            }
        }
        __syncthreads();   // gates ready

        // ---- phase C: per-(s,j) LSTM cell update, writes new h1
        {
            float gi = gsm[sA][jA];
            float gf = gsm[sA][H + jA];
            float gg = gsm[sA][2 * H + jA];
            float go = gsm[sA][3 * H + jA];
            c1A = sigmoidf_(gf) * c1A + sigmoidf_(gi) * tanhf_(gg);
            h1s[sA][jA] = sigmoidf_(go) * tanhf_(c1A);
        }
        if (hasB) {
            float gi = gsm[sB][jB];
            float gf = gsm[sB][H + jB];
            float gg = gsm[sB][2 * H + jB];
            float go = gsm[sB][3 * H + jB];
            c1B = sigmoidf_(gf) * c1B + sigmoidf_(gi) * tanhf_(gg);
            h1s[sB][jB] = sigmoidf_(go) * tanhf_(c1B);
        }
        __syncthreads();   // h1 ready

        // ---- phase E: layer 2 (warp0 lanes 0..15; overlaps other warps' next phase A)
        if (tid < 16) {
            const ull* hp = (const ull*)(&h1s[s2][0]);
            ull acc0 = 0, acc1 = 0;
#pragma unroll
            for (int p = 0; p < NP; p += 2) {
                acc0 = ffma2(w2p[g2][p],     hp[p],     acc0);
                acc1 = ffma2(w2p[g2][p + 1], hp[p + 1], acc1);
            }
            float gate = lo2(acc0) + hi2(acc0) + lo2(acc1) + hi2(acc1)
                       + whh2g * h2r + b2sum;
            float act = (g2 == 2) ? tanhf_(gate) : sigmoidf_(gate);
            int base = tid & ~3;
            float vi = __shfl_sync(0x0000FFFFu, act, base + 0);
            float vf = __shfl_sync(0x0000FFFFu, act, base + 1);
            float vg = __shfl_sync(0x0000FFFFu, act, base + 2);
            float vo = __shfl_sync(0x0000FFFFu, act, base + 3);
            c2r = vf * c2r + vi * vg;
            h2r = vo * tanhf_(c2r);
            if (g2 == 0) h2buf[s2][tp] = h2r;
        }

        // ---- coalesced output flush once per tile (warp 0)
        if (tp == (XT - 1) && tid < 32) {
            __syncwarp();
            int tbase = t - (XT - 1);
#pragma unroll
            for (int s = 0; s < S; ++s)
                out[(seq0 + s) * T_LEN + tbase + tid] = h2buf[s][tid];
        }
    }
}

extern "C" void kernel_launch(void* const* d_in, const int* in_sizes, int n_in,
                              void* d_out, int out_size) {
    const float* stim = (const float*)d_in[0];
    const float* Wih1 = (const float*)d_in[1];
    const float* Whh1 = (const float*)d_in[2];
    const float* bih1 = (const float*)d_in[3];
    const float* bhh1 = (const float*)d_in[4];
    const float* Wih2 = (const float*)d_in[5];
    const float* Whh2 = (const float*)d_in[6];
    const float* bih2 = (const float*)d_in[7];
    const float* bhh2 = (const float*)d_in[8];
    float* out = (float*)d_out;

    lstm2_kernel<<<N_SEQ / S, TPB>>>(stim, Wih1, Whh1, bih1, bhh1,
                                     Wih2, Whh2, bih2, bhh2, out);
}

// round 4
// speedup vs baseline: 1.6702x; 1.6702x over previous
#include <cuda_runtime.h>
#include <cuda_bf16.h>

typedef unsigned long long ull;

#define H      51
#define G4     204        // 4*H
#define HP     52         // padded hidden (even, for f32x2 pairs)
#define NP     26         // packed h-pairs per gate row
#define NQ     13         // 128-bit quads per h vector
#define T_LEN  2048
#define N_SEQ  1024
#define S      4          // sequences per block
#define TPB    128
#define XT     32         // stimulus prefetch tile (steps)

// ---------------- f32x2 helpers (Blackwell packed fp32) ----------------
__device__ __forceinline__ ull ffma2(ull a, ull b, ull c) {
    ull d;
    asm("fma.rn.f32x2 %0, %1, %2, %3;" : "=l"(d) : "l"(a), "l"(b), "l"(c));
    return d;
}
__device__ __forceinline__ ull pack2(float lo, float hi) {
    ull d;
    asm("mov.b64 %0, {%1, %2};" : "=l"(d) : "f"(lo), "f"(hi));
    return d;
}
__device__ __forceinline__ float lo2(ull v) { return __uint_as_float((unsigned)v); }
__device__ __forceinline__ float hi2(ull v) { return __uint_as_float((unsigned)(v >> 32)); }

// ---------------- activations: HW MUFU.TANH ---------------------------
__device__ __forceinline__ float tanh_fast(float x) {
    float y;
    asm("tanh.approx.f32 %0, %1;" : "=f"(y) : "f"(x));
    return y;
}
__device__ __forceinline__ float sig_fast(float x) {
    return fmaf(0.5f, tanh_fast(0.5f * x), 0.5f);
}

__global__ void __launch_bounds__(TPB, 2) lstm2_kernel(
    const float* __restrict__ stim,
    const float* __restrict__ Wih1, const float* __restrict__ Whh1,
    const float* __restrict__ bih1, const float* __restrict__ bhh1,
    const float* __restrict__ Wih2, const float* __restrict__ Whh2,
    const float* __restrict__ bih2, const float* __restrict__ bhh2,
    float* __restrict__ out)
{
    __shared__ __align__(16) float h1s[S][HP];     // layer-1 hidden state (padded, [51]=0)
    __shared__ float gsm[S][G4];                   // layer-1 pre-activation gates
    __shared__ float xbuf[2][S][XT];               // double-buffered stimulus tiles
    __shared__ float h2buf[S][XT];                 // layer-2 outputs, flushed per tile
    __shared__ __align__(16) ull w2p[4][NP];       // W_ih2 packed along h

    const int tid  = threadIdx.x;
    const int seq0 = blockIdx.x * S;

    // ---- layer-1 gate-row assignment: thread owns rows r0=tid, r1=tid+128 (if <204)
    const int  r0   = tid;
    const bool has1 = (tid + TPB) < G4;           // tid < 76
    const int  r1   = has1 ? (tid + TPB) : 0;
    const bool warp_has1 = (tid < 96);            // warps 0-2 carry a second row

    // recurrent weights packed along h, register-resident
    ull w0[NP], w1[NP];
#pragma unroll
    for (int p = 0; p < NP; ++p) {
        float a0 = Whh1[r0 * H + 2 * p];
        float a1 = (2 * p + 1 < H) ? Whh1[r0 * H + 2 * p + 1] : 0.0f;
        w0[p] = pack2(a0, a1);
        float b0v = has1 ? Whh1[r1 * H + 2 * p] : 0.0f;
        float b1v = (has1 && (2 * p + 1 < H)) ? Whh1[r1 * H + 2 * p + 1] : 0.0f;
        w1[p] = pack2(b0v, b1v);
    }
    const float bs0 = bih1[r0] + bhh1[r0];
    const float bs1 = has1 ? (bih1[r1] + bhh1[r1]) : 0.0f;
    const float wi0 = Wih1[r0];
    const float wi1 = has1 ? Wih1[r1] : 0.0f;

    // ---- elementwise task assignment: task = (s,j) flat id; A = tid, B = tid+128
    const int  idA = tid;                  // 0..127 < 204
    const int  sA = idA / H, jA = idA % H;
    const bool hasB = tid < (G4 - TPB);    // tid < 76
    const int  idB = hasB ? (tid + TPB) : 0;
    const int  sB = idB / H, jB = idB % H;
    float c1A = 0.0f, c1B = 0.0f;

    // ---- layer-2 state: lanes 0..15 of warp 0, thread = (s2, g2)
    float whh2g = 0.0f, b2sum = 0.0f, h2r = 0.0f, c2r = 0.0f;
    int s2 = 0, g2 = 0;
    if (tid < 16) {
        s2 = tid >> 2; g2 = tid & 3;
        whh2g = Whh2[g2];
        b2sum = bih2[g2] + bhh2[g2];
    }

    // ---- init shared memory
    for (int i = tid; i < S * HP; i += TPB) (&h1s[0][0])[i] = 0.0f;
    if (tid < 4) {
#pragma unroll
        for (int p = 0; p < NP; ++p) {
            float a = Wih2[tid * H + 2 * p];
            float b = (2 * p + 1 < H) ? Wih2[tid * H + 2 * p + 1] : 0.0f;
            w2p[tid][p] = pack2(a, b);
        }
    }
    // stimulus prefetch (warp 3): tile 0 -> smem, tile 1 -> regs
    float xr[S];
    if (tid >= 96) {
        int lane = tid - 96;
#pragma unroll
        for (int s = 0; s < S; ++s)
            xbuf[0][s][lane] = stim[(seq0 + s) * T_LEN + lane];
#pragma unroll
        for (int s = 0; s < S; ++s)
            xr[s] = stim[(seq0 + s) * T_LEN + XT + lane];
    }
    __syncthreads();

    for (int t = 0; t < T_LEN; ++t) {
        const int cur = (t >> 5) & 1;
        const int tp  = t & (XT - 1);

        // ---- tile boundary: publish prefetched x tile, start next LDG
        if (tp == 0 && t != 0) {
            if (tid >= 96) {
                int lane = tid - 96;
#pragma unroll
                for (int s = 0; s < S; ++s) xbuf[cur][s][lane] = xr[s];
                int nt = t + XT;
                if (nt < T_LEN) {
#pragma unroll
                    for (int s = 0; s < S; ++s)
                        xr[s] = stim[(seq0 + s) * T_LEN + nt + lane];
                }
            }
            __syncthreads();
        }

        // ---- phase A: gates = W_hh1 @ h1 + b + x*W_ih1  (f32x2, LDS.128 h loads)
        if (warp_has1) {
            // warps 0-2: two gate rows per thread
#pragma unroll
            for (int s = 0; s < S; ++s) {
                const ulonglong2* hq = (const ulonglong2*)(&h1s[s][0]);
                ull a00 = 0, a01 = 0, a10 = 0, a11 = 0;
#pragma unroll
                for (int q = 0; q < NQ; ++q) {
                    ulonglong2 hv = hq[q];
                    a00 = ffma2(w0[2 * q],     hv.x, a00);
                    a10 = ffma2(w1[2 * q],     hv.x, a10);
                    a01 = ffma2(w0[2 * q + 1], hv.y, a01);
                    a11 = ffma2(w1[2 * q + 1], hv.y, a11);
                }
                const float xv = xbuf[cur][s][tp];
                float g0 = lo2(a00) + hi2(a00) + lo2(a01) + hi2(a01) + bs0 + xv * wi0;
                gsm[s][r0] = g0;
                if (has1) {
                    float g1 = lo2(a10) + hi2(a10) + lo2(a11) + hi2(a11) + bs1 + xv * wi1;
                    gsm[s][r1] = g1;
                }
            }
        } else {
            // warp 3: single gate row per thread (rows 96..127)
#pragma unroll
            for (int s = 0; s < S; ++s) {
                const ulonglong2* hq = (const ulonglong2*)(&h1s[s][0]);
                ull a00 = 0, a01 = 0;
#pragma unroll
                for (int q = 0; q < NQ; ++q) {
                    ulonglong2 hv = hq[q];
                    a00 = ffma2(w0[2 * q],     hv.x, a00);
                    a01 = ffma2(w0[2 * q + 1], hv.y, a01);
                }
                const float xv = xbuf[cur][s][tp];
                float g0 = lo2(a00) + hi2(a00) + lo2(a01) + hi2(a01) + bs0 + xv * wi0;
                gsm[s][r0] = g0;
            }
        }
        __syncthreads();   // gates ready

        // ---- phase C: per-(s,j) LSTM cell update (MUFU.TANH), writes new h1
        {
            float gi = gsm[sA][jA];
            float gf = gsm[sA][H + jA];
            float gg = gsm[sA][2 * H + jA];
            float go = gsm[sA][3 * H + jA];
            c1A = sig_fast(gf) * c1A + sig_fast(gi) * tanh_fast(gg);
            h1s[sA][jA] = sig_fast(go) * tanh_fast(c1A);
        }
        if (hasB) {
            float gi = gsm[sB][jB];
            float gf = gsm[sB][H + jB];
            float gg = gsm[sB][2 * H + jB];
            float go = gsm[sB][3 * H + jB];
            c1B = sig_fast(gf) * c1B + sig_fast(gi) * tanh_fast(gg);
            h1s[sB][jB] = sig_fast(go) * tanh_fast(c1B);
        }
        __syncthreads();   // h1 ready

        // ---- phase E: layer 2 (warp0 lanes 0..15; overlaps other warps' next phase A)
        if (tid < 16) {
            const ulonglong2* hq = (const ulonglong2*)(&h1s[s2][0]);
            const ulonglong2* wq = (const ulonglong2*)(&w2p[g2][0]);
            ull acc0 = 0, acc1 = 0;
#pragma unroll
            for (int q = 0; q < NQ; ++q) {
                ulonglong2 hv = hq[q];
                ulonglong2 wv = wq[q];
                acc0 = ffma2(wv.x, hv.x, acc0);
                acc1 = ffma2(wv.y, hv.y, acc1);
            }
            float gate = lo2(acc0) + hi2(acc0) + lo2(acc1) + hi2(acc1)
                       + whh2g * h2r + b2sum;
            float act = (g2 == 2) ? tanh_fast(gate) : sig_fast(gate);
            int base = tid & ~3;
            float vi = __shfl_sync(0x0000FFFFu, act, base + 0);
            float vf = __shfl_sync(0x0000FFFFu, act, base + 1);
            float vg = __shfl_sync(0x0000FFFFu, act, base + 2);
            float vo = __shfl_sync(0x0000FFFFu, act, base + 3);
            c2r = vf * c2r + vi * vg;
            h2r = vo * tanh_fast(c2r);
            if (g2 == 0) h2buf[s2][tp] = h2r;
        }

        // ---- coalesced output flush once per tile (warp 0)
        if (tp == (XT - 1) && tid < 32) {
            __syncwarp();
            int tbase = t - (XT - 1);
#pragma unroll
            for (int s = 0; s < S; ++s)
                out[(seq0 + s) * T_LEN + tbase + tid] = h2buf[s][tid];
        }
    }
}

extern "C" void kernel_launch(void* const* d_in, const int* in_sizes, int n_in,
                              void* d_out, int out_size) {
    const float* stim = (const float*)d_in[0];
    const float* Wih1 = (const float*)d_in[1];
    const float* Whh1 = (const float*)d_in[2];
    const float* bih1 = (const float*)d_in[3];
    const float* bhh1 = (const float*)d_in[4];
    const float* Wih2 = (const float*)d_in[5];
    const float* Whh2 = (const float*)d_in[6];
    const float* bih2 = (const float*)d_in[7];
    const float* bhh2 = (const float*)d_in[8];
    float* out = (float*)d_out;

    lstm2_kernel<<<N_SEQ / S, TPB>>>(stim, Wih1, Whh1, bih1, bhh1,
                                     Wih2, Whh2, bih2, bhh2, out);
}